// round 4
// baseline (speedup 1.0000x reference)
#include <cuda_runtime.h>
#include <cuda_bf16.h>
#include <math.h>

// Problem constants
static constexpr int BB   = 4;
static constexpr int SS   = 2048;
static constexpr int DM   = 768;
static constexpr int HH   = 12;
static constexpr int DH   = 64;
static constexpr int NTOK = BB * SS;          // 8192
static constexpr float EPS = 1e-5f;

// Scratch (device globals: no allocation)
__device__ float g_Q  [NTOK * DM];
__device__ float g_K  [NTOK * DM];
__device__ float g_V  [NTOK * DM];
__device__ float g_Ctx[NTOK * DM];
__device__ float g_Hid[NTOK * 2 * DM];
__device__ float g_H  [NTOK * DM];

// ---------------------------------------------------------------------------
// Generic SGEMM: C[M,N] = A[M,K] @ W[K,N] + bias, with fused epilogue.
// EPI = 0: bias only; 1: bias + ReLU; 2: bias + residual (res[M,N])
// 128x128 tile, BK=8, 256 threads, 8x8 per-thread microtile.
// ---------------------------------------------------------------------------
template <int EPI>
__global__ __launch_bounds__(256) void gemm_kernel(
    const float* __restrict__ A, const float* __restrict__ W,
    const float* __restrict__ bias, const float* __restrict__ res,
    float* __restrict__ C, int M, int N, int K)
{
    __shared__ float Ast[8][132];   // transposed A tile, padded
    __shared__ float Bs [8][128];

    const int tid = threadIdx.x;
    const int tx  = tid & 15;
    const int ty  = tid >> 4;
    const int m0  = blockIdx.y * 128;
    const int n0  = blockIdx.x * 128;

    const float* Aptr = A + (size_t)(m0 + (tid >> 1)) * K + (tid & 1) * 4;
    const float* Bptr = W + (size_t)(tid >> 5) * N + n0 + (tid & 31) * 4;

    float c[8][8];
#pragma unroll
    for (int i = 0; i < 8; i++)
#pragma unroll
        for (int j = 0; j < 8; j++) c[i][j] = 0.f;

    float4 av = *(const float4*)(Aptr);
    float4 bv = *(const float4*)(Bptr);

    for (int kt = 0; kt < K; kt += 8) {
        __syncthreads();
        Ast[(tid & 1) * 4 + 0][tid >> 1] = av.x;
        Ast[(tid & 1) * 4 + 1][tid >> 1] = av.y;
        Ast[(tid & 1) * 4 + 2][tid >> 1] = av.z;
        Ast[(tid & 1) * 4 + 3][tid >> 1] = av.w;
        *(float4*)&Bs[tid >> 5][(tid & 31) * 4] = bv;
        __syncthreads();

        if (kt + 8 < K) {
            av = *(const float4*)(Aptr + kt + 8);
            bv = *(const float4*)(Bptr + (size_t)(kt + 8) * N);
        }

#pragma unroll
        for (int k = 0; k < 8; k++) {
            float4 a0 = *(float4*)&Ast[k][ty * 4];
            float4 a1 = *(float4*)&Ast[k][64 + ty * 4];
            float4 b0 = *(float4*)&Bs[k][tx * 4];
            float4 b1 = *(float4*)&Bs[k][64 + tx * 4];
            float ar[8] = {a0.x, a0.y, a0.z, a0.w, a1.x, a1.y, a1.z, a1.w};
            float br[8] = {b0.x, b0.y, b0.z, b0.w, b1.x, b1.y, b1.z, b1.w};
#pragma unroll
            for (int i = 0; i < 8; i++)
#pragma unroll
                for (int j = 0; j < 8; j++)
                    c[i][j] += ar[i] * br[j];
        }
    }

    // Epilogue
#pragma unroll
    for (int i = 0; i < 8; i++) {
        int r = m0 + ((i < 4) ? (ty * 4 + i) : (64 + ty * 4 + i - 4));
#pragma unroll
        for (int jh = 0; jh < 2; jh++) {
            int cc = n0 + jh * 64 + tx * 4;
            float4 bb = *(const float4*)(bias + cc);
            float4 v;
            v.x = c[i][jh * 4 + 0] + bb.x;
            v.y = c[i][jh * 4 + 1] + bb.y;
            v.z = c[i][jh * 4 + 2] + bb.z;
            v.w = c[i][jh * 4 + 3] + bb.w;
            if (EPI == 1) {
                v.x = fmaxf(v.x, 0.f); v.y = fmaxf(v.y, 0.f);
                v.z = fmaxf(v.z, 0.f); v.w = fmaxf(v.w, 0.f);
            }
            if (EPI == 2) {
                float4 rr = *(const float4*)(res + (size_t)r * N + cc);
                v.x += rr.x; v.y += rr.y; v.z += rr.z; v.w += rr.w;
            }
            *(float4*)(C + (size_t)r * N + cc) = v;
        }
    }
}

// ---------------------------------------------------------------------------
// Flash attention (fp32, no mask). One CTA per (b, h, 64-row q tile).
// 256 threads; thread (ty,tx) computes S rows ty*4..+3, cols {tx+16*b},
// and O rows ty*4..+3, cols tx*4..+3.
// ---------------------------------------------------------------------------
__global__ __launch_bounds__(256) void attn_kernel(
    const float* __restrict__ Q, const float* __restrict__ K,
    const float* __restrict__ V, float* __restrict__ Ctx)
{
    extern __shared__ float sm[];
    const int LD = 68;
    float* Qs = sm;
    float* Ks = sm + 64 * LD;
    float* Vs = sm + 2 * 64 * LD;
    float* Ps = sm + 3 * 64 * LD;

    const int tid = threadIdx.x;
    const int tx  = tid & 15;
    const int ty  = tid >> 4;
    const int b   = blockIdx.z;
    const int h   = blockIdx.y;
    const int q0  = blockIdx.x * 64;

    // Load Q tile (64 rows x 64 cols of this head)
#pragma unroll
    for (int ii = 0; ii < 4; ii++) {
        int idx = tid + 256 * ii;
        int row = idx >> 4, c4 = idx & 15;
        *(float4*)&Qs[row * LD + c4 * 4] =
            *(const float4*)(Q + ((size_t)(b * SS + q0 + row) * DM + h * DH + c4 * 4));
    }

    float o[4][4];
    float m[4], l[4];
#pragma unroll
    for (int a = 0; a < 4; a++) {
        m[a] = -1e30f; l[a] = 0.f;
#pragma unroll
        for (int j = 0; j < 4; j++) o[a][j] = 0.f;
    }

    for (int k0 = 0; k0 < SS; k0 += 64) {
        __syncthreads();
#pragma unroll
        for (int ii = 0; ii < 4; ii++) {
            int idx = tid + 256 * ii;
            int row = idx >> 4, c4 = idx & 15;
            size_t g = (size_t)(b * SS + k0 + row) * DM + h * DH + c4 * 4;
            *(float4*)&Ks[row * LD + c4 * 4] = *(const float4*)(K + g);
            *(float4*)&Vs[row * LD + c4 * 4] = *(const float4*)(V + g);
        }
        __syncthreads();

        // S = Q @ K^T
        float s[4][4];
#pragma unroll
        for (int a = 0; a < 4; a++)
#pragma unroll
            for (int bb = 0; bb < 4; bb++) s[a][bb] = 0.f;

#pragma unroll
        for (int d4 = 0; d4 < 16; d4++) {
            float4 qv[4], kv[4];
#pragma unroll
            for (int a = 0; a < 4; a++)
                qv[a] = *(float4*)&Qs[(ty * 4 + a) * LD + d4 * 4];
#pragma unroll
            for (int bb = 0; bb < 4; bb++)
                kv[bb] = *(float4*)&Ks[(tx + 16 * bb) * LD + d4 * 4];
#pragma unroll
            for (int a = 0; a < 4; a++)
#pragma unroll
                for (int bb = 0; bb < 4; bb++)
                    s[a][bb] += qv[a].x * kv[bb].x + qv[a].y * kv[bb].y +
                                qv[a].z * kv[bb].z + qv[a].w * kv[bb].w;
        }

        // Online softmax (rows owned by a 16-lane group; reduce over tx)
#pragma unroll
        for (int a = 0; a < 4; a++) {
#pragma unroll
            for (int bb = 0; bb < 4; bb++) s[a][bb] *= 0.125f;  // 1/sqrt(64)
            float mx = fmaxf(fmaxf(s[a][0], s[a][1]), fmaxf(s[a][2], s[a][3]));
#pragma unroll
            for (int off = 1; off < 16; off <<= 1)
                mx = fmaxf(mx, __shfl_xor_sync(0xffffffffu, mx, off));
            float mnew = fmaxf(m[a], mx);
            float corr = __expf(m[a] - mnew);
            m[a] = mnew;
            float rs = 0.f;
#pragma unroll
            for (int bb = 0; bb < 4; bb++) {
                float p = __expf(s[a][bb] - mnew);
                s[a][bb] = p;
                rs += p;
            }
#pragma unroll
            for (int off = 1; off < 16; off <<= 1)
                rs += __shfl_xor_sync(0xffffffffu, rs, off);
            l[a] = l[a] * corr + rs;
#pragma unroll
            for (int j = 0; j < 4; j++) o[a][j] *= corr;
#pragma unroll
            for (int bb = 0; bb < 4; bb++)
                Ps[(ty * 4 + a) * LD + tx + 16 * bb] = s[a][bb];
        }
        __syncwarp();

        // O += P @ V
#pragma unroll 4
        for (int j = 0; j < 64; j++) {
            float4 vv = *(float4*)&Vs[j * LD + tx * 4];
#pragma unroll
            for (int a = 0; a < 4; a++) {
                float p = Ps[(ty * 4 + a) * LD + j];
                o[a][0] += p * vv.x; o[a][1] += p * vv.y;
                o[a][2] += p * vv.z; o[a][3] += p * vv.w;
            }
        }
        __syncwarp();
    }

    // Finalize and store context (back to [token, D] layout)
#pragma unroll
    for (int a = 0; a < 4; a++) {
        float inv = 1.f / l[a];
        float4 v;
        v.x = o[a][0] * inv; v.y = o[a][1] * inv;
        v.z = o[a][2] * inv; v.w = o[a][3] * inv;
        *(float4*)(Ctx + ((size_t)(b * SS + q0 + ty * 4 + a) * DM + h * DH + tx * 4)) = v;
    }
}

// ---------------------------------------------------------------------------
// LayerNorm over last dim (768), one block per token row.
// ---------------------------------------------------------------------------
__global__ __launch_bounds__(256) void ln_kernel(
    const float* __restrict__ Hbuf, const float* __restrict__ gamma,
    const float* __restrict__ beta, float* __restrict__ out)
{
    __shared__ float red[16];
    const int row = blockIdx.x;
    const float* hp = Hbuf + (size_t)row * DM;

    float v[3];
    float sum = 0.f, sq = 0.f;
#pragma unroll
    for (int i = 0; i < 3; i++) {
        v[i] = hp[threadIdx.x + 256 * i];
        sum += v[i];
        sq  += v[i] * v[i];
    }
#pragma unroll
    for (int off = 16; off > 0; off >>= 1) {
        sum += __shfl_xor_sync(0xffffffffu, sum, off);
        sq  += __shfl_xor_sync(0xffffffffu, sq,  off);
    }
    const int wid = threadIdx.x >> 5, lane = threadIdx.x & 31;
    if (lane == 0) { red[wid] = sum; red[8 + wid] = sq; }
    __syncthreads();
    float ts = 0.f, tq = 0.f;
#pragma unroll
    for (int w = 0; w < 8; w++) { ts += red[w]; tq += red[8 + w]; }

    const float mean = ts * (1.f / (float)DM);
    const float var  = tq * (1.f / (float)DM) - mean * mean;
    const float rstd = rsqrtf(var + EPS);

#pragma unroll
    for (int i = 0; i < 3; i++) {
        int cIdx = threadIdx.x + 256 * i;
        out[(size_t)row * DM + cIdx] = (v[i] - mean) * rstd * gamma[cIdx] + beta[cIdx];
    }
}

// ---------------------------------------------------------------------------
// Launch
// ---------------------------------------------------------------------------
extern "C" void kernel_launch(void* const* d_in, const int* in_sizes, int n_in,
                              void* d_out, int out_size)
{
    const float* x     = (const float*)d_in[0];
    const float* Wq    = (const float*)d_in[1];
    const float* bq    = (const float*)d_in[2];
    const float* Wk    = (const float*)d_in[3];
    const float* bk    = (const float*)d_in[4];
    const float* Wv    = (const float*)d_in[5];
    const float* bv    = (const float*)d_in[6];
    const float* W1    = (const float*)d_in[7];
    const float* b1    = (const float*)d_in[8];
    const float* W2    = (const float*)d_in[9];
    const float* b2    = (const float*)d_in[10];
    const float* gamma = (const float*)d_in[11];
    const float* beta  = (const float*)d_in[12];
    float* out = (float*)d_out;

    void *pQ, *pK, *pV, *pCtx, *pHid, *pH;
    cudaGetSymbolAddress(&pQ,   g_Q);
    cudaGetSymbolAddress(&pK,   g_K);
    cudaGetSymbolAddress(&pV,   g_V);
    cudaGetSymbolAddress(&pCtx, g_Ctx);
    cudaGetSymbolAddress(&pHid, g_Hid);
    cudaGetSymbolAddress(&pH,   g_H);

    const int smem_attn = 4 * 64 * 68 * (int)sizeof(float);  // 69632 B
    cudaFuncSetAttribute(attn_kernel, cudaFuncAttributeMaxDynamicSharedMemorySize,
                         smem_attn);

    dim3 blk(256);

    // QKV projections
    dim3 gQKV(DM / 128, NTOK / 128);  // (6, 64)
    gemm_kernel<0><<<gQKV, blk>>>(x, Wq, bq, nullptr, (float*)pQ, NTOK, DM, DM);
    gemm_kernel<0><<<gQKV, blk>>>(x, Wk, bk, nullptr, (float*)pK, NTOK, DM, DM);
    gemm_kernel<0><<<gQKV, blk>>>(x, Wv, bv, nullptr, (float*)pV, NTOK, DM, DM);

    // Attention
    dim3 gAttn(SS / 64, HH, BB);      // (32, 12, 4)
    attn_kernel<<<gAttn, blk, smem_attn>>>((const float*)pQ, (const float*)pK,
                                           (const float*)pV, (float*)pCtx);

    // MLP: hidden = relu(ctx @ W1 + b1); h = hidden @ W2 + b2 + x
    dim3 gM1(2 * DM / 128, NTOK / 128);  // (12, 64)
    gemm_kernel<1><<<gM1, blk>>>((const float*)pCtx, W1, b1, nullptr,
                                 (float*)pHid, NTOK, 2 * DM, DM);
    dim3 gM2(DM / 128, NTOK / 128);      // (6, 64)
    gemm_kernel<2><<<gM2, blk>>>((const float*)pHid, W2, b2, x,
                                 (float*)pH, NTOK, DM, 2 * DM);

    // LayerNorm -> output
    ln_kernel<<<NTOK, blk>>>((const float*)pH, gamma, beta, out);
}